// round 1
// baseline (speedup 1.0000x reference)
#include <cuda_runtime.h>
#include <math.h>

#define M_TOTAL 184320
#define IMG 256
#define ORTHO_F (1.0f/256.0f)

// scratch for k-space data-consistency result (complex), static device alloc
__device__ float2 g_kdc[M_TOTAL];

__device__ __forceinline__ float2 cmulf(float2 a, float2 b){
    return make_float2(a.x*b.x - a.y*b.y, a.x*b.y + a.y*b.x);
}
__device__ __forceinline__ float2 conjf2(float2 a){ return make_float2(a.x, -a.y); }

// w^n for integer n (may be negative), |n| <= 256. ~8 iterations max.
__device__ __forceinline__ float2 cpow_int(float2 w, int n){
    if (n < 0){ w = conjf2(w); n = -n; }
    float2 r = make_float2(1.f, 0.f);
    float2 t = w;
    while (n){
        if (n & 1) r = cmulf(r, t);
        t = cmulf(t, t);
        n >>= 1;
    }
    return r;
}

// ============================================================================
// Forward kernel: for each k-sample m, A[m] = ORTHO * sum_{u,w} img[u,w]
//   * e^{-i kx_m (u-128)} * e^{-i ky_m (w-128)}
// Structured as GEMM over u:  C[m,w] = sum_u Ex[m,u] * img[u,w]
// then epilogue reduction over w with Ey, then DC blend -> g_kdc[m].
//
// Block: 32 m-rows, full w (256), K = u (256) in steps of 8.
// 256 threads: warp = m-group (4 m's), lane = w-group (8 w's, stride 32).
// ============================================================================
__global__ __launch_bounds__(256) void fwd_kernel(
    const float* __restrict__ img,      // (256,256,2)
    const float* __restrict__ y_radial, // (640,288,2)
    const float* __restrict__ lambda_p, // (1,)
    const float* __restrict__ ktraj)    // kx[M] then ky[M]
{
    __shared__ float2 smA[8][32];       // Ex tile [k][m]
    __shared__ float4 smB4[8][128];     // img rows [k][w pairs] (8 rows x 256 complex)

    const int tid  = threadIdx.x;
    const int lane = tid & 31;
    const int warp = tid >> 5;
    const int m_base = blockIdx.x * 32;

    float2 acc[4][8];
    #pragma unroll
    for (int i = 0; i < 4; i++)
        #pragma unroll
        for (int j = 0; j < 8; j++) acc[i][j] = make_float2(0.f, 0.f);

    // warp 0, lane l owns recurrence state for m-row l
    float2 cur = make_float2(1.f, 0.f);
    float2 wx  = make_float2(1.f, 0.f);
    if (warp == 0){
        float kx = ktraj[m_base + lane];
        float s, c; sincosf(kx, &s, &c);
        wx  = make_float2(c, -s);          // e^{-i kx}
        cur = cpow_int(wx, -128);          // e^{-i kx * (-128)}
    }

    for (int u0 = 0; u0 < 256; u0 += 8){
        __syncthreads();
        if (warp == 0){
            #pragma unroll
            for (int k = 0; k < 8; k++){
                smA[k][lane] = cur;        // Ex[m, u0+k]
                cur = cmulf(cur, wx);
            }
        }
        // load 8 image rows (16 KB) coalesced as float4
        const float4* gB = (const float4*)(img + (size_t)u0 * IMG * 2);
        #pragma unroll
        for (int p = 0; p < 4; p++){
            int idx = p * 256 + tid;       // 0..1023
            ((float4*)smB4)[idx] = gB[idx];
        }
        __syncthreads();

        const float2* smB = (const float2*)smB4;
        #pragma unroll
        for (int k = 0; k < 8; k++){
            float4 a01 = *((const float4*)&smA[k][warp*4]);
            float4 a23 = *((const float4*)&smA[k][warp*4 + 2]);
            float2 a[4];
            a[0] = make_float2(a01.x, a01.y);
            a[1] = make_float2(a01.z, a01.w);
            a[2] = make_float2(a23.x, a23.y);
            a[3] = make_float2(a23.z, a23.w);
            #pragma unroll
            for (int j = 0; j < 8; j++){
                float2 b = smB[k*256 + lane + 32*j];
                #pragma unroll
                for (int i = 0; i < 4; i++){
                    acc[i][j].x = fmaf(a[i].x, b.x, acc[i][j].x);
                    acc[i][j].x = fmaf(-a[i].y, b.y, acc[i][j].x);
                    acc[i][j].y = fmaf(a[i].x, b.y, acc[i][j].y);
                    acc[i][j].y = fmaf(a[i].y, b.x, acc[i][j].y);
                }
            }
        }
    }

    // Epilogue: A_m = sum_w Ey[m,w] * C[m,w], then blend.
    float lam = 1.f / (1.f + expf(-lambda_p[0]));

    #pragma unroll
    for (int i = 0; i < 4; i++){
        int m = m_base + warp*4 + i;
        float ky = ktraj[M_TOTAL + m];
        float s, c; sincosf(ky, &s, &c);
        float2 wy = make_float2(c, -s);    // e^{-i ky}

        // e = wy^{lane-128}; w32 = wy^32 (step between this thread's w's)
        float2 t = wy, r = make_float2(1.f, 0.f);
        int e_ = lane;
        #pragma unroll
        for (int b = 0; b < 5; b++){
            if (e_ & 1) r = cmulf(r, t);
            t = cmulf(t, t);
            e_ >>= 1;
        }
        float2 w32  = t;                    // wy^32
        float2 w64  = cmulf(t, t);
        float2 w128 = cmulf(w64, w64);
        float2 e    = cmulf(r, conjf2(w128));  // wy^{lane-128}

        float2 part = make_float2(0.f, 0.f);
        #pragma unroll
        for (int j = 0; j < 8; j++){
            part.x += e.x*acc[i][j].x - e.y*acc[i][j].y;
            part.y += e.x*acc[i][j].y + e.y*acc[i][j].x;
            e = cmulf(e, w32);
        }
        #pragma unroll
        for (int off = 16; off > 0; off >>= 1){
            part.x += __shfl_xor_sync(0xffffffffu, part.x, off);
            part.y += __shfl_xor_sync(0xffffffffu, part.y, off);
        }
        if (lane == 0){
            float kx  = ktraj[m];
            float dcf = sqrtf(kx*kx + ky*ky);
            float a_re = part.x * ORTHO_F;
            float a_im = part.y * ORTHO_F;
            int tt = m % 640;
            int ss = m / 640;
            const float* yp = y_radial + ((size_t)tt*288 + ss)*2;
            float2 kd;
            kd.x = lam*dcf*a_re + (1.f - lam)*yp[0];
            kd.y = lam*dcf*a_im + (1.f - lam)*yp[1];
            g_kdc[m] = kd;
        }
    }
}

// ============================================================================
// Adjoint kernel: x[u,v] = ORTHO * sum_m k_m * e^{+i kx_m (u-128)} * e^{+i ky_m (v-128)}
// GEMM with K = M (split-K over blockIdx.z), output tile 64x64.
// 256 threads: tx = tid&15 (v-group, 4 v's stride 16), ty = tid>>4 (u-group, 4 u's).
// Operand tiles generated per K-step by 32 threads (warp0 lanes<16: A; warp1 lanes<16: B).
// ============================================================================
#define CHUNK 1536
#define BKA   16
#define PADR  66   // float2 per smem row (pad: keeps 16B align, kills STS conflicts)

__global__ __launch_bounds__(256) void adj_kernel(
    const float* __restrict__ ktraj,
    float* __restrict__ out)
{
    __shared__ float2 smA[BKA][PADR];  // e^{+i kx (u-128)}, local u 0..63
    __shared__ float2 smB[BKA][PADR];  // ORTHO * k_m * e^{+i ky (v-128)}, local v 0..63

    const int tid  = threadIdx.x;
    const int lane = tid & 31;
    const int warp = tid >> 5;
    const int tx = tid & 15;
    const int ty = tid >> 4;
    const int u_base = blockIdx.y * 64;
    const int v_base = blockIdx.x * 64;
    const int m0 = blockIdx.z * CHUNK;

    float2 acc[4][4];
    #pragma unroll
    for (int i = 0; i < 4; i++)
        #pragma unroll
        for (int j = 0; j < 4; j++) acc[i][j] = make_float2(0.f, 0.f);

    for (int step = 0; step < CHUNK/BKA; ++step){
        __syncthreads();
        if (warp == 0 && lane < 16){
            // A gen: one thread per m in this BK slab, 64 u-values by recurrence
            int m = m0 + step*BKA + lane;
            float kx = ktraj[m];
            float s, c; sincosf(kx, &s, &c);
            float2 w = make_float2(c, s);          // e^{+i kx}
            float2 e = cpow_int(w, u_base - 128);  // seed at local u = 0
            #pragma unroll
            for (int i = 0; i < 64; i++){
                smA[lane][i] = e;
                e = cmulf(e, w);
            }
        } else if (warp == 1 && lane < 16){
            int m = m0 + step*BKA + lane;
            float ky = ktraj[M_TOTAL + m];
            float s, c; sincosf(ky, &s, &c);
            float2 w = make_float2(c, s);          // e^{+i ky}
            float2 e = cpow_int(w, v_base - 128);
            float2 km = g_kdc[m];
            km.x *= ORTHO_F; km.y *= ORTHO_F;
            #pragma unroll
            for (int i = 0; i < 64; i++){
                smB[lane][i] = cmulf(km, e);
                e = cmulf(e, w);
            }
        }
        __syncthreads();

        #pragma unroll
        for (int k = 0; k < BKA; k++){
            float4 a01 = *((const float4*)&smA[k][ty*4]);
            float4 a23 = *((const float4*)&smA[k][ty*4 + 2]);
            float2 a[4];
            a[0] = make_float2(a01.x, a01.y);
            a[1] = make_float2(a01.z, a01.w);
            a[2] = make_float2(a23.x, a23.y);
            a[3] = make_float2(a23.z, a23.w);
            #pragma unroll
            for (int j = 0; j < 4; j++){
                float2 b = smB[k][tx + 16*j];
                #pragma unroll
                for (int i = 0; i < 4; i++){
                    acc[i][j].x = fmaf(a[i].x, b.x, acc[i][j].x);
                    acc[i][j].x = fmaf(-a[i].y, b.y, acc[i][j].x);
                    acc[i][j].y = fmaf(a[i].x, b.y, acc[i][j].y);
                    acc[i][j].y = fmaf(a[i].y, b.x, acc[i][j].y);
                }
            }
        }
    }

    // split-K accumulate into output
    #pragma unroll
    for (int i = 0; i < 4; i++){
        int u = u_base + ty*4 + i;
        #pragma unroll
        for (int j = 0; j < 4; j++){
            int v = v_base + tx + 16*j;
            float* p = out + ((size_t)u*256 + v)*2;
            atomicAdd(p,     acc[i][j].x);
            atomicAdd(p + 1, acc[i][j].y);
        }
    }
}

__global__ void zero_kernel(float* out, int n){
    int i = blockIdx.x * 256 + threadIdx.x;
    if (i < n) out[i] = 0.f;
}

extern "C" void kernel_launch(void* const* d_in, const int* in_sizes, int n_in,
                              void* d_out, int out_size)
{
    const float* x   = (const float*)d_in[0];  // (1,1,256,256,2)
    const float* y   = (const float*)d_in[1];  // (640,288,2)
    const float* lp  = (const float*)d_in[2];  // (1,)
    const float* kt  = (const float*)d_in[3];  // (1,2,184320)
    float* out = (float*)d_out;                // (1,1,256,256,2)

    fwd_kernel<<<M_TOTAL/32, 256>>>(x, y, lp, kt);
    zero_kernel<<<(out_size + 255)/256, 256>>>(out, out_size);
    adj_kernel<<<dim3(4, 4, M_TOTAL/CHUNK), 256>>>(kt, out);
}